// round 6
// baseline (speedup 1.0000x reference)
#include <cuda_runtime.h>
#include <cstdint>

#define B_    2
#define S_    1024
#define HQ_   32
#define HKV_  8
#define D_    128
#define BQ    128
#define BK    64
#define NT    512
#define QSTR  132
#define KSTR  132
#define VSTR  136

// smem word offsets
#define W_Q    0
#define W_K0   16896
#define W_K1   25344
#define W_V0   33792
#define W_V1   42496
#define W_MLX  51200
#define W_TOT  51456          // 205,824 bytes

static __device__ __forceinline__ uint32_t f2tf(float x) {
    uint32_t u; asm("cvt.rna.tf32.f32 %0, %1;" : "=r"(u) : "f"(x)); return u;
}
static __device__ __forceinline__ void mma8(float* d, const uint32_t* a,
                                            uint32_t b0, uint32_t b1) {
    asm volatile(
        "mma.sync.aligned.m16n8k8.row.col.f32.tf32.tf32.f32 "
        "{%0,%1,%2,%3}, {%4,%5,%6,%7}, {%8,%9}, {%0,%1,%2,%3};"
        : "+f"(d[0]), "+f"(d[1]), "+f"(d[2]), "+f"(d[3])
        : "r"(a[0]), "r"(a[1]), "r"(a[2]), "r"(a[3]), "r"(b0), "r"(b1));
}
static __device__ __forceinline__ uint4 cvt4(float4 v) {
    uint4 u; u.x = f2tf(v.x); u.y = f2tf(v.y); u.z = f2tf(v.z); u.w = f2tf(v.w);
    return u;
}

// -------------------------------------------------------------------------
// KV-cache scatter (unchanged — negligible)
// -------------------------------------------------------------------------
__global__ void kv_scatter_kernel(const float* __restrict__ xk,
                                  const float* __restrict__ xv,
                                  const int* __restrict__ idx,
                                  float* __restrict__ kvout) {
    int t = blockIdx.x * blockDim.x + threadIdx.x;
    const int total = B_ * S_ * 2 * HKV_ * (D_ / 4);
    if (t >= total) return;
    int d4 = t & 31;
    int hh = (t >> 5) & 15;
    int i  = t >> 9;
    float4 v;
    if (hh < HKV_)
        v = reinterpret_cast<const float4*>(xk)[(i * HKV_ + hh) * 32 + d4];
    else
        v = reinterpret_cast<const float4*>(xv)[(i * HKV_ + (hh - HKV_)) * 32 + d4];
    int row = idx[i];
    reinterpret_cast<float4*>(kvout)[((size_t)row * 16 + hh) * 32 + d4] = v;
}

// -------------------------------------------------------------------------
// Pipelined split-K tf32 flash attention.
// 16 warps: wq=w>>1 owns q rows 16*wq..+15; wk=w&1 owns keys wk*32..+31 of
// each 64-key tile. Private online-softmax chains; two-way merge at end.
// Double-buffered K/V (one barrier/tile); K/V for kt+1 prefetched into
// registers at loop-top, stored after compute. P never touches smem: the
// S->P(A-fragment) relayout is an intra-quad shfl permutation.
// -------------------------------------------------------------------------
__global__ __launch_bounds__(NT, 1)
void attn_mma(const float* __restrict__ xq, const float* __restrict__ xk,
              const float* __restrict__ xv, float* __restrict__ out) {
    extern __shared__ uint32_t sm[];
    uint32_t* Qs = sm + W_Q;
    float* mlx = (float*)(sm + W_MLX);
    float* Ored = (float*)(sm + W_Q);     // epilogue alias over Qs

    const int tid = threadIdx.x, w = tid >> 5, lane = tid & 31;
    const int wq = w >> 1, wk = w & 1;
    const int g = lane >> 2, t = lane & 3;
    const int qt = (S_ / BQ - 1) - blockIdx.x;
    const int h = blockIdx.y, b = blockIdx.z, hk = h >> 2;
    const int m0 = wq * 16, ko = wk * 32;
    const int r0loc = m0 + g, r1loc = m0 + g + 8;
    const float scale = 0.08838834764831845f;   // 1/sqrt(128)
    const int srcA = (lane & ~3) | (t >> 1);
    const int srcB = srcA + 2;

    // ---- Q tile: global -> smem (scaled, tf32) ----
#pragma unroll
    for (int i = 0; i < 8; ++i) {
        int it = tid + i * NT;
        int r = it >> 5, c4 = (it & 31) << 2;
        float4 v = *reinterpret_cast<const float4*>(
            xq + ((((size_t)b * S_ + (size_t)qt * BQ + r) * HQ_ + h) * D_ + c4));
        v.x *= scale; v.y *= scale; v.z *= scale; v.w *= scale;
        *reinterpret_cast<uint4*>(Qs + r * QSTR + c4) = cvt4(v);
    }
    // ---- K/V tile 0 -> buffer 0 ----
#pragma unroll
    for (int i = 0; i < 4; ++i) {
        int it = tid + i * NT;
        int r = it >> 5, c4 = (it & 31) << 2;
        size_t ga = (((size_t)b * S_ + r) * HKV_ + hk) * D_ + c4;
        *reinterpret_cast<uint4*>(sm + W_K0 + r * KSTR + c4) =
            cvt4(*reinterpret_cast<const float4*>(xk + ga));
        *reinterpret_cast<uint4*>(sm + W_V0 + r * VSTR + c4) =
            cvt4(*reinterpret_cast<const float4*>(xv + ga));
    }
    __syncthreads();

    float Oa[16][4];
#pragma unroll
    for (int n = 0; n < 16; ++n)
#pragma unroll
        for (int c = 0; c < 4; ++c) Oa[n][c] = 0.0f;
    float mr0 = -1e30f, mr1 = -1e30f, lr0 = 0.0f, lr1 = 0.0f;
    const int n64 = 2 * qt + 2;

    for (int kt = 0; kt < n64; ++kt) {
        const int p = kt & 1;
        const uint32_t* Kb = sm + (p ? W_K1 : W_K0);
        const uint32_t* Vb = sm + (p ? W_V1 : W_V0);
        uint32_t* Kn = sm + (p ? W_K0 : W_K1);
        uint32_t* Vn = sm + (p ? W_V0 : W_V1);

        // ---- prefetch next tile into registers (stored after compute) ----
        const bool pre = (kt + 1 < n64);
        float4 pk[4], pv[4];
        if (pre) {
#pragma unroll
            for (int i = 0; i < 4; ++i) {
                int it = tid + i * NT;
                int r = it >> 5, c4 = (it & 31) << 2;
                size_t ga = (((size_t)b * S_ + (size_t)(kt + 1) * BK + r) * HKV_ + hk)
                            * D_ + c4;
                pk[i] = *reinterpret_cast<const float4*>(xk + ga);
                pv[i] = *reinterpret_cast<const float4*>(xv + ga);
            }
        }

        // ---- QK^T on own 32-key slice: S(16x32) ----
        float Sa[4][4];
#pragma unroll
        for (int n = 0; n < 4; ++n)
#pragma unroll
            for (int c = 0; c < 4; ++c) Sa[n][c] = 0.0f;
#pragma unroll
        for (int kk = 0; kk < 16; ++kk) {
            uint32_t qa[4];
            const uint32_t* qp = Qs + r0loc * QSTR + kk * 8 + t;
            qa[0] = qp[0]; qa[1] = qp[8 * QSTR];
            qa[2] = qp[4]; qa[3] = qp[8 * QSTR + 4];
#pragma unroll
            for (int n = 0; n < 4; ++n) {
                const uint32_t* kb = Kb + (ko + n * 8 + g) * KSTR + kk * 8 + t;
                mma8(Sa[n], qa, kb[0], kb[4]);
            }
        }

        // ---- causal mask (last two 64-key tiles straddle the diagonal) ----
        if (kt >= 2 * qt) {
            const int qg0 = qt * BQ + r0loc, qg1 = qg0 + 8;
            const int kb0 = kt * BK + ko;
#pragma unroll
            for (int n = 0; n < 4; ++n) {
                int c = kb0 + n * 8 + 2 * t;
                if (c     > qg0) Sa[n][0] = -1e30f;
                if (c + 1 > qg0) Sa[n][1] = -1e30f;
                if (c     > qg1) Sa[n][2] = -1e30f;
                if (c + 1 > qg1) Sa[n][3] = -1e30f;
            }
        }

        // ---- private online softmax ----
        float t0 = -1e30f, t1 = -1e30f;
#pragma unroll
        for (int n = 0; n < 4; ++n) {
            t0 = fmaxf(t0, fmaxf(Sa[n][0], Sa[n][1]));
            t1 = fmaxf(t1, fmaxf(Sa[n][2], Sa[n][3]));
        }
        t0 = fmaxf(t0, __shfl_xor_sync(0xffffffffu, t0, 1));
        t0 = fmaxf(t0, __shfl_xor_sync(0xffffffffu, t0, 2));
        t1 = fmaxf(t1, __shfl_xor_sync(0xffffffffu, t1, 1));
        t1 = fmaxf(t1, __shfl_xor_sync(0xffffffffu, t1, 2));
        const float M0 = fmaxf(mr0, t0), M1 = fmaxf(mr1, t1);
        const float f0 = __expf(mr0 - M0), f1 = __expf(mr1 - M1);
        mr0 = M0; mr1 = M1;

        float s0 = 0.0f, s1 = 0.0f;
        uint32_t Pt[4][4];
#pragma unroll
        for (int n = 0; n < 4; ++n) {
            float p00 = __expf(Sa[n][0] - M0), p01 = __expf(Sa[n][1] - M0);
            float p10 = __expf(Sa[n][2] - M1), p11 = __expf(Sa[n][3] - M1);
            s0 += p00 + p01; s1 += p10 + p11;
            Pt[n][0] = f2tf(p00); Pt[n][1] = f2tf(p01);
            Pt[n][2] = f2tf(p10); Pt[n][3] = f2tf(p11);
        }
        s0 += __shfl_xor_sync(0xffffffffu, s0, 1);
        s0 += __shfl_xor_sync(0xffffffffu, s0, 2);
        s1 += __shfl_xor_sync(0xffffffffu, s1, 1);
        s1 += __shfl_xor_sync(0xffffffffu, s1, 2);
        lr0 = lr0 * f0 + s0;
        lr1 = lr1 * f1 + s1;

        // ---- store prefetched K (LDG long since landed) ----
        if (pre) {
#pragma unroll
            for (int i = 0; i < 4; ++i) {
                int it = tid + i * NT;
                int r = it >> 5, c4 = (it & 31) << 2;
                *reinterpret_cast<uint4*>(Kn + r * KSTR + c4) = cvt4(pk[i]);
            }
        }

        // ---- rescale O; PV with shfl-built P A-fragments ----
#pragma unroll
        for (int n = 0; n < 16; ++n) {
            Oa[n][0] *= f0; Oa[n][1] *= f0; Oa[n][2] *= f1; Oa[n][3] *= f1;
        }
#pragma unroll
        for (int kk = 0; kk < 4; ++kk) {
            uint32_t w0 = __shfl_sync(0xffffffffu, Pt[kk][0], srcA);
            uint32_t w1 = __shfl_sync(0xffffffffu, Pt[kk][1], srcA);
            uint32_t w2 = __shfl_sync(0xffffffffu, Pt[kk][2], srcA);
            uint32_t w3 = __shfl_sync(0xffffffffu, Pt[kk][3], srcA);
            uint32_t x0 = __shfl_sync(0xffffffffu, Pt[kk][0], srcB);
            uint32_t x1 = __shfl_sync(0xffffffffu, Pt[kk][1], srcB);
            uint32_t x2 = __shfl_sync(0xffffffffu, Pt[kk][2], srcB);
            uint32_t x3 = __shfl_sync(0xffffffffu, Pt[kk][3], srcB);
            uint32_t af[4];
            af[0] = (t & 1) ? w1 : w0;   // P[g][t]
            af[1] = (t & 1) ? w3 : w2;   // P[g+8][t]
            af[2] = (t & 1) ? x1 : x0;   // P[g][t+4]
            af[3] = (t & 1) ? x3 : x2;   // P[g+8][t+4]
#pragma unroll
            for (int n = 0; n < 16; ++n) {
                const uint32_t* vb = Vb + (ko + kk * 8 + t) * VSTR + n * 8 + g;
                mma8(Oa[n], af, vb[0], vb[4 * VSTR]);
            }
        }

        // ---- store prefetched V ----
        if (pre) {
#pragma unroll
            for (int i = 0; i < 4; ++i) {
                int it = tid + i * NT;
                int r = it >> 5, c4 = (it & 31) << 2;
                *reinterpret_cast<uint4*>(Vn + r * VSTR + c4) = cvt4(pv[i]);
            }
        }
        __syncthreads();   // buf[1-p] complete; all reads of buf[p] done
    }

    // ---- epilogue: two-way flash merge of the private halves ----
    if (wk == 1) {
#pragma unroll
        for (int n = 0; n < 16; ++n) {
            float* o0 = Ored + r0loc * 132 + n * 8 + 2 * t;
            o0[0] = Oa[n][0]; o0[1] = Oa[n][1];
            float* o1 = Ored + r1loc * 132 + n * 8 + 2 * t;
            o1[0] = Oa[n][2]; o1[1] = Oa[n][3];
        }
        if (t == 0) {
            mlx[2 * r0loc] = mr0; mlx[2 * r0loc + 1] = lr0;
            mlx[2 * r1loc] = mr1; mlx[2 * r1loc + 1] = lr1;
        }
    }
    __syncthreads();
    if (wk == 0) {
        const float m1a = mlx[2 * r0loc], l1a = mlx[2 * r0loc + 1];
        const float m1b = mlx[2 * r1loc], l1b = mlx[2 * r1loc + 1];
        const float Ma = fmaxf(mr0, m1a), Mb = fmaxf(mr1, m1b);
        const float c0a = __expf(mr0 - Ma), c1a = __expf(m1a - Ma);
        const float c0b = __expf(mr1 - Mb), c1b = __expf(m1b - Mb);
        const float inva = 1.0f / (lr0 * c0a + l1a * c1a);
        const float invb = 1.0f / (lr1 * c0b + l1b * c1b);
        const int q0g = qt * BQ + r0loc, q1g = qt * BQ + r1loc;
        float* ob0 = out + (((size_t)b * S_ + q0g) * HQ_ + h) * D_;
        float* ob1 = out + (((size_t)b * S_ + q1g) * HQ_ + h) * D_;
#pragma unroll
        for (int n = 0; n < 16; ++n) {
            int col = n * 8 + 2 * t;
            float2 o0, o1;
            o0.x = (Oa[n][0] * c0a + Ored[r0loc * 132 + col]     * c1a) * inva;
            o0.y = (Oa[n][1] * c0a + Ored[r0loc * 132 + col + 1] * c1a) * inva;
            o1.x = (Oa[n][2] * c0b + Ored[r1loc * 132 + col]     * c1b) * invb;
            o1.y = (Oa[n][3] * c0b + Ored[r1loc * 132 + col + 1] * c1b) * invb;
            *reinterpret_cast<float2*>(ob0 + col) = o0;
            *reinterpret_cast<float2*>(ob1 + col) = o1;
        }
    }
}

// -------------------------------------------------------------------------
extern "C" void kernel_launch(void* const* d_in, const int* in_sizes, int n_in,
                              void* d_out, int out_size) {
    const float* xq    = (const float*)d_in[0];
    const float* xk    = (const float*)d_in[1];
    const float* xv    = (const float*)d_in[2];
    const float* kvbuf = (const float*)d_in[3];
    const int*   idx   = (const int*)d_in[4];

    float* out   = (float*)d_out;
    float* kvout = out + (size_t)B_ * S_ * HQ_ * D_;

    cudaMemcpyAsync(kvout, kvbuf, (size_t)B_ * S_ * 2 * HKV_ * D_ * sizeof(float),
                    cudaMemcpyDeviceToDevice, 0);
    const int nvec = B_ * S_ * 2 * HKV_ * (D_ / 4);
    kv_scatter_kernel<<<(nvec + 255) / 256, 256>>>(xk, xv, idx, kvout);

    const int smem_bytes = W_TOT * (int)sizeof(uint32_t);   // 205,824
    cudaFuncSetAttribute(attn_mma,
                         cudaFuncAttributeMaxDynamicSharedMemorySize, smem_bytes);
    attn_mma<<<dim3(S_ / BQ, HQ_, B_), NT, smem_bytes>>>(xq, xk, xv, out);
}

// round 7
// speedup vs baseline: 1.0651x; 1.0651x over previous
#include <cuda_runtime.h>
#include <cstdint>

#define B_    2
#define S_    1024
#define HQ_   32
#define HKV_  8
#define D_    128
#define BQ    64
#define BK    64
#define NT    256
#define QSTR  132
#define KSTR  132   // K tile, aliased by P tile (barrier-separated)
#define VSTR  136

// smem word offsets
#define W_Q    0
#define W_KP   8448
#define W_V    16896
#define W_MLX  25600
#define W_TOT  25728          // 102,912 bytes per CTA -> 2 CTAs/SM

static __device__ __forceinline__ uint32_t f2tf(float x) {
    uint32_t u; asm("cvt.rna.tf32.f32 %0, %1;" : "=r"(u) : "f"(x)); return u;
}
static __device__ __forceinline__ void mma8(float* d, const uint32_t* a,
                                            uint32_t b0, uint32_t b1) {
    asm volatile(
        "mma.sync.aligned.m16n8k8.row.col.f32.tf32.tf32.f32 "
        "{%0,%1,%2,%3}, {%4,%5,%6,%7}, {%8,%9}, {%0,%1,%2,%3};"
        : "+f"(d[0]), "+f"(d[1]), "+f"(d[2]), "+f"(d[3])
        : "r"(a[0]), "r"(a[1]), "r"(a[2]), "r"(a[3]), "r"(b0), "r"(b1));
}
static __device__ __forceinline__ uint4 cvt4(float4 v) {
    uint4 u; u.x = f2tf(v.x); u.y = f2tf(v.y); u.z = f2tf(v.z); u.w = f2tf(v.w);
    return u;
}

// -------------------------------------------------------------------------
// KV-cache scatter (unchanged — negligible)
// -------------------------------------------------------------------------
__global__ void kv_scatter_kernel(const float* __restrict__ xk,
                                  const float* __restrict__ xv,
                                  const int* __restrict__ idx,
                                  float* __restrict__ kvout) {
    int t = blockIdx.x * blockDim.x + threadIdx.x;
    const int total = B_ * S_ * 2 * HKV_ * (D_ / 4);
    if (t >= total) return;
    int d4 = t & 31;
    int hh = (t >> 5) & 15;
    int i  = t >> 9;
    float4 v;
    if (hh < HKV_)
        v = reinterpret_cast<const float4*>(xk)[(i * HKV_ + hh) * 32 + d4];
    else
        v = reinterpret_cast<const float4*>(xv)[(i * HKV_ + (hh - HKV_)) * 32 + d4];
    int row = idx[i];
    reinterpret_cast<float4*>(kvout)[((size_t)row * 16 + hh) * 32 + d4] = v;
}

// -------------------------------------------------------------------------
// Split-K tf32 flash attention, 2 CTAs/SM.
// CTA = (b, h, 64-q-row tile), 8 warps: wq=w>>1 owns q rows 16*wq..+15;
// wk=w&1 owns key cols wk*32..+31 of each 64-key tile. Fully private
// online-softmax chains per warp; two-way flash merge in the epilogue.
// P aliases K (barrier-separated). R5-proven structure, halved CTA.
// -------------------------------------------------------------------------
__global__ __launch_bounds__(NT, 2)
void attn_mma(const float* __restrict__ xq, const float* __restrict__ xk,
              const float* __restrict__ xv, float* __restrict__ out) {
    extern __shared__ uint32_t sm[];
    uint32_t* Qs  = sm + W_Q;              // [64][QSTR]
    uint32_t* KPs = sm + W_KP;             // K tile, then P tile [64][KSTR]
    float* mlx  = (float*)(sm + W_MLX);    // [64][2]: (m, l) from wk=1
    float* Ored = (float*)(sm + W_Q);      // epilogue alias over Qs

    const int tid = threadIdx.x, w = tid >> 5, lane = tid & 31;
    const int wq = w >> 1, wk = w & 1;
    const int g = lane >> 2, t = lane & 3;
    const int qt = (S_ / BQ - 1) - blockIdx.x;   // big tiles first
    const int h = blockIdx.y, b = blockIdx.z, hk = h >> 2;
    const int m0 = wq * 16, ko = wk * 32;
    const int r0loc = m0 + g, r1loc = m0 + g + 8;
    const float scale = 0.08838834764831845f;    // 1/sqrt(128)

    // ---- Q tile: global -> smem (scaled, tf32) ----
#pragma unroll
    for (int i = 0; i < 8; ++i) {
        int it = tid + i * NT;
        int r = it >> 5, c4 = (it & 31) << 2;
        float4 v = *reinterpret_cast<const float4*>(
            xq + ((((size_t)b * S_ + (size_t)qt * BQ + r) * HQ_ + h) * D_ + c4));
        v.x *= scale; v.y *= scale; v.z *= scale; v.w *= scale;
        *reinterpret_cast<uint4*>(Qs + r * QSTR + c4) = cvt4(v);
    }

    float Oa[16][4];
#pragma unroll
    for (int n = 0; n < 16; ++n)
#pragma unroll
        for (int c = 0; c < 4; ++c) Oa[n][c] = 0.0f;
    float mr0 = -1e30f, mr1 = -1e30f, lr0 = 0.0f, lr1 = 0.0f;

    for (int kt = 0; kt <= qt; ++kt) {
        __syncthreads();   // B1: prior tile's P/V readers done (kt=0: Q stores)

        // ---- K,V tile: global -> smem (tf32) ----
#pragma unroll
        for (int i = 0; i < 8; ++i) {
            int it = tid + i * NT;
            int r = it >> 5, c4 = (it & 31) << 2;
            size_t ga = (((size_t)b * S_ + (size_t)kt * BK + r) * HKV_ + hk) * D_ + c4;
            *reinterpret_cast<uint4*>(KPs + r * KSTR + c4) =
                cvt4(*reinterpret_cast<const float4*>(xk + ga));
            *reinterpret_cast<uint4*>(sm + W_V + r * VSTR + c4) =
                cvt4(*reinterpret_cast<const float4*>(xv + ga));
        }
        __syncthreads();   // B2: K/V visible

        // ---- QK^T on own 32-key slice: S(16x32) ----
        float Sa[4][4];
#pragma unroll
        for (int n = 0; n < 4; ++n)
#pragma unroll
            for (int c = 0; c < 4; ++c) Sa[n][c] = 0.0f;
#pragma unroll
        for (int kk = 0; kk < 16; ++kk) {
            uint32_t qa[4];
            const uint32_t* qp = Qs + r0loc * QSTR + kk * 8 + t;
            qa[0] = qp[0]; qa[1] = qp[8 * QSTR];
            qa[2] = qp[4]; qa[3] = qp[8 * QSTR + 4];
#pragma unroll
            for (int n = 0; n < 4; ++n) {
                const uint32_t* kb = KPs + (ko + n * 8 + g) * KSTR + kk * 8 + t;
                mma8(Sa[n], qa, kb[0], kb[4]);
            }
        }

        // ---- causal mask (diag tile only; BK==BQ so local compare) ----
        if (kt == qt) {
#pragma unroll
            for (int n = 0; n < 4; ++n) {
                int c = ko + n * 8 + 2 * t;
                if (c     > r0loc) Sa[n][0] = -1e30f;
                if (c + 1 > r0loc) Sa[n][1] = -1e30f;
                if (c     > r1loc) Sa[n][2] = -1e30f;
                if (c + 1 > r1loc) Sa[n][3] = -1e30f;
            }
        }

        // ---- private online softmax ----
        float t0 = -1e30f, t1 = -1e30f;
#pragma unroll
        for (int n = 0; n < 4; ++n) {
            t0 = fmaxf(t0, fmaxf(Sa[n][0], Sa[n][1]));
            t1 = fmaxf(t1, fmaxf(Sa[n][2], Sa[n][3]));
        }
        t0 = fmaxf(t0, __shfl_xor_sync(0xffffffffu, t0, 1));
        t0 = fmaxf(t0, __shfl_xor_sync(0xffffffffu, t0, 2));
        t1 = fmaxf(t1, __shfl_xor_sync(0xffffffffu, t1, 1));
        t1 = fmaxf(t1, __shfl_xor_sync(0xffffffffu, t1, 2));
        const float M0 = fmaxf(mr0, t0), M1 = fmaxf(mr1, t1);
        const float f0 = __expf(mr0 - M0), f1 = __expf(mr1 - M1);
        mr0 = M0; mr1 = M1;

        __syncthreads();   // B3: ALL warps' K reads done -> P may overwrite K

        float s0 = 0.0f, s1 = 0.0f;
#pragma unroll
        for (int n = 0; n < 4; ++n) {
            float p00 = __expf(Sa[n][0] - M0), p01 = __expf(Sa[n][1] - M0);
            float p10 = __expf(Sa[n][2] - M1), p11 = __expf(Sa[n][3] - M1);
            s0 += p00 + p01; s1 += p10 + p11;
            uint32_t* pr0 = KPs + r0loc * KSTR + ko + n * 8 + 2 * t;
            pr0[0] = f2tf(p00); pr0[1] = f2tf(p01);
            uint32_t* pr1 = KPs + r1loc * KSTR + ko + n * 8 + 2 * t;
            pr1[0] = f2tf(p10); pr1[1] = f2tf(p11);
        }
        s0 += __shfl_xor_sync(0xffffffffu, s0, 1);
        s0 += __shfl_xor_sync(0xffffffffu, s0, 2);
        s1 += __shfl_xor_sync(0xffffffffu, s1, 1);
        s1 += __shfl_xor_sync(0xffffffffu, s1, 2);
        lr0 = lr0 * f0 + s0;
        lr1 = lr1 * f1 + s1;
        __syncwarp();      // P block is warp-private: intra-warp visibility

        // ---- rescale O, PV on own key slice ----
#pragma unroll
        for (int n = 0; n < 16; ++n) {
            Oa[n][0] *= f0; Oa[n][1] *= f0; Oa[n][2] *= f1; Oa[n][3] *= f1;
        }
#pragma unroll
        for (int kk = 0; kk < 4; ++kk) {
            uint32_t af[4];
            const uint32_t* p0 = KPs + r0loc * KSTR + ko + kk * 8 + t;
            const uint32_t* p1 = p0 + 8 * KSTR;
            af[0] = p0[0]; af[1] = p1[0]; af[2] = p0[4]; af[3] = p1[4];
#pragma unroll
            for (int n = 0; n < 16; ++n) {
                const uint32_t* vb = sm + W_V + (ko + kk * 8 + t) * VSTR + n * 8 + g;
                mma8(Oa[n], af, vb[0], vb[4 * VSTR]);
            }
        }
    }

    // ---- epilogue: two-way flash merge of the private halves ----
    __syncthreads();       // main loop fully done; Qs dead -> reuse as Ored
    if (wk == 1) {
#pragma unroll
        for (int n = 0; n < 16; ++n) {
            float* o0 = Ored + r0loc * 132 + n * 8 + 2 * t;
            o0[0] = Oa[n][0]; o0[1] = Oa[n][1];
            float* o1 = Ored + r1loc * 132 + n * 8 + 2 * t;
            o1[0] = Oa[n][2]; o1[1] = Oa[n][3];
        }
        if (t == 0) {
            mlx[2 * r0loc] = mr0; mlx[2 * r0loc + 1] = lr0;
            mlx[2 * r1loc] = mr1; mlx[2 * r1loc + 1] = lr1;
        }
    }
    __syncthreads();
    if (wk == 0) {
        const float m1a = mlx[2 * r0loc], l1a = mlx[2 * r0loc + 1];
        const float m1b = mlx[2 * r1loc], l1b = mlx[2 * r1loc + 1];
        const float Ma = fmaxf(mr0, m1a), Mb = fmaxf(mr1, m1b);
        const float c0a = __expf(mr0 - Ma), c1a = __expf(m1a - Ma);
        const float c0b = __expf(mr1 - Mb), c1b = __expf(m1b - Mb);
        const float inva = 1.0f / (lr0 * c0a + l1a * c1a);
        const float invb = 1.0f / (lr1 * c0b + l1b * c1b);
        const int q0g = qt * BQ + r0loc, q1g = qt * BQ + r1loc;
        float* ob0 = out + (((size_t)b * S_ + q0g) * HQ_ + h) * D_;
        float* ob1 = out + (((size_t)b * S_ + q1g) * HQ_ + h) * D_;
#pragma unroll
        for (int n = 0; n < 16; ++n) {
            int col = n * 8 + 2 * t;
            float2 o0, o1;
            o0.x = (Oa[n][0] * c0a + Ored[r0loc * 132 + col]     * c1a) * inva;
            o0.y = (Oa[n][1] * c0a + Ored[r0loc * 132 + col + 1] * c1a) * inva;
            o1.x = (Oa[n][2] * c0b + Ored[r1loc * 132 + col]     * c1b) * invb;
            o1.y = (Oa[n][3] * c0b + Ored[r1loc * 132 + col + 1] * c1b) * invb;
            *reinterpret_cast<float2*>(ob0 + col) = o0;
            *reinterpret_cast<float2*>(ob1 + col) = o1;
        }
    }
}

// -------------------------------------------------------------------------
extern "C" void kernel_launch(void* const* d_in, const int* in_sizes, int n_in,
                              void* d_out, int out_size) {
    const float* xq    = (const float*)d_in[0];
    const float* xk    = (const float*)d_in[1];
    const float* xv    = (const float*)d_in[2];
    const float* kvbuf = (const float*)d_in[3];
    const int*   idx   = (const int*)d_in[4];

    float* out   = (float*)d_out;
    float* kvout = out + (size_t)B_ * S_ * HQ_ * D_;

    cudaMemcpyAsync(kvout, kvbuf, (size_t)B_ * S_ * 2 * HKV_ * D_ * sizeof(float),
                    cudaMemcpyDeviceToDevice, 0);
    const int nvec = B_ * S_ * 2 * HKV_ * (D_ / 4);
    kv_scatter_kernel<<<(nvec + 255) / 256, 256>>>(xk, xv, idx, kvout);

    const int smem_bytes = W_TOT * (int)sizeof(uint32_t);   // 102,912
    cudaFuncSetAttribute(attn_mma,
                         cudaFuncAttributeMaxDynamicSharedMemorySize, smem_bytes);
    attn_mma<<<dim3(S_ / BQ, HQ_, B_), NT, smem_bytes>>>(xq, xk, xv, out);
}